// round 2
// baseline (speedup 1.0000x reference)
#include <cuda_runtime.h>
#include <cstdint>

// TVLoss: circular-gradient magnitude mean.
//   gx[i,j] = f[i,j] - f[i,(j+1)%W]
//   gy[i,j] = f[i,j] - f[(i+1)%H,j]
//   out = mean( sqrt(gx^2 + gy^2) )
// (Reference's FFT path is exactly this circular convolution.)

static constexpr int B = 32, C = 3, H = 512, W = 512;
static constexpr long long TOTAL = (long long)B * C * H * W;   // 25,165,824
static constexpr int NV4   = (int)(TOTAL / 4);                 // 6,291,456 float4
static constexpr int W4    = W / 4;                            // 128 float4 per row
static constexpr int NBLK  = 1184;                             // 148 SMs * 8
static constexpr int NTHR  = 256;

__device__ float g_partials[NBLK];

__global__ __launch_bounds__(NTHR)
void tv_stage1(const float4* __restrict__ in4) {
    const float* __restrict__ inf = (const float*)in4;
    float acc = 0.0f;

    const int stride = gridDim.x * blockDim.x;
    for (int g = blockIdx.x * blockDim.x + threadIdx.x; g < NV4; g += stride) {
        // g is the linear float4 index; self load is simply in4[g].
        const int row = g >> 7;          // global row (plane*H + i), 512 floats/row
        const int c4  = g & (W4 - 1);    // float4 column within row
        const int i   = row & (H - 1);   // row within the HxW plane
        const int drow = (i == H - 1) ? row - (H - 1) : row + 1;  // circular down

        const float4 s = in4[g];
        const float4 d = in4[(drow << 7) + c4];
        // right neighbor of the last lane: column (4*c4+4) mod W
        const float  r = inf[(row << 9) + (((c4 + 1) & (W4 - 1)) << 2)];

        const float dx0 = s.x - s.y;
        const float dx1 = s.y - s.z;
        const float dx2 = s.z - s.w;
        const float dx3 = s.w - r;
        const float dy0 = s.x - d.x;
        const float dy1 = s.y - d.y;
        const float dy2 = s.z - d.z;
        const float dy3 = s.w - d.w;

        acc += sqrtf(fmaf(dx0, dx0, dy0 * dy0));
        acc += sqrtf(fmaf(dx1, dx1, dy1 * dy1));
        acc += sqrtf(fmaf(dx2, dx2, dy2 * dy2));
        acc += sqrtf(fmaf(dx3, dx3, dy3 * dy3));
    }

    // warp reduce
    #pragma unroll
    for (int o = 16; o; o >>= 1) acc += __shfl_xor_sync(0xFFFFFFFFu, acc, o);

    __shared__ float smem[NTHR / 32];
    if ((threadIdx.x & 31) == 0) smem[threadIdx.x >> 5] = acc;
    __syncthreads();

    if (threadIdx.x < 32) {
        float v = (threadIdx.x < NTHR / 32) ? smem[threadIdx.x] : 0.0f;
        #pragma unroll
        for (int o = 16; o; o >>= 1) v += __shfl_xor_sync(0xFFFFFFFFu, v, o);
        if (threadIdx.x == 0) g_partials[blockIdx.x] = v;
    }
}

__global__ __launch_bounds__(1024)
void tv_stage2(float* __restrict__ out) {
    __shared__ double sm[1024];
    double v = 0.0;
    for (int i = threadIdx.x; i < NBLK; i += 1024) v += (double)g_partials[i];
    sm[threadIdx.x] = v;
    __syncthreads();
    #pragma unroll
    for (int s = 512; s; s >>= 1) {
        if (threadIdx.x < s) sm[threadIdx.x] += sm[threadIdx.x + s];
        __syncthreads();
    }
    if (threadIdx.x == 0) out[0] = (float)(sm[0] / (double)TOTAL);
}

extern "C" void kernel_launch(void* const* d_in, const int* in_sizes, int n_in,
                              void* d_out, int out_size) {
    const float4* in4 = (const float4*)d_in[0];
    float* out = (float*)d_out;
    tv_stage1<<<NBLK, NTHR>>>(in4);
    tv_stage2<<<1, 1024>>>(out);
}

// round 4
// speedup vs baseline: 1.6757x; 1.6757x over previous
#include <cuda_runtime.h>
#include <cstdint>

// TVLoss: circular-gradient magnitude mean (== reference's FFT path).
//   gx[i,j] = f[i,j] - f[i,(j+1)%W]
//   gy[i,j] = f[i,j] - f[(i+1)%H,j]
//   out = mean( sqrt(gx^2 + gy^2) )
//
// Single fused kernel: vertical-strip traversal (next-row load doubles as
// down-neighbor -> ~1x read traffic), shfl for right-neighbor, last-block
// final reduction (no second kernel launch).

static constexpr int B = 32, C = 3, H = 512, W = 512;
static constexpr long long TOTAL = (long long)B * C * H * W;   // 25,165,824
static constexpr int PLANES = B * C;                           // 96
static constexpr int W4     = W / 4;                           // 128 float4/row
static constexpr int KROWS  = 16;                              // strip height
static constexpr int STRIPS = H / KROWS;                       // 32 per plane
static constexpr int NTHR   = 256;                             // 2 strips/block
static constexpr int NBLK   = PLANES * STRIPS * W4 / NTHR;     // 1536

__device__ float    g_partials[NBLK];
__device__ unsigned g_count = 0;

__device__ __forceinline__ float fsqrt_approx(float x) {
    float r;
    asm("sqrt.approx.f32 %0, %1;" : "=f"(r) : "f"(x));
    return r;
}

__global__ __launch_bounds__(NTHR)
void tv_fused(const float4* __restrict__ in4, float* __restrict__ out) {
    const float* __restrict__ inf = (const float*)in4;

    const int tid  = threadIdx.x;
    const int c4   = tid & (W4 - 1);             // column (float4 units)
    const int sid  = blockIdx.x * 2 + (tid >> 7);// global strip id
    const int pl   = sid >> 5;                   // plane (0..95)
    const int st   = sid & (STRIPS - 1);         // strip within plane
    const int row0 = st * KROWS;

    const int planeBase = pl << 16;              // plane * 512 * 128 (float4)
    const int lane = tid & 31;

    float acc = 0.0f;

    float4 s = in4[planeBase + (row0 << 7) + c4];

    #pragma unroll
    for (int k = 0; k < KROWS; k++) {
        const int row  = row0 + k;
        const int nrow = (row + 1) & (H - 1);    // circular within plane
        const float4 d = in4[planeBase + (nrow << 7) + c4];

        // right neighbor of s.w = x-component of column c4+1
        float rn = __shfl_down_sync(0xFFFFFFFFu, s.x, 1);
        if (lane == 31) {
            const int rc4 = (c4 + 1) & (W4 - 1);
            rn = inf[(planeBase << 2) + (row << 9) + (rc4 << 2)];
        }

        const float dx0 = s.x - s.y;
        const float dx1 = s.y - s.z;
        const float dx2 = s.z - s.w;
        const float dx3 = s.w - rn;
        const float dy0 = s.x - d.x;
        const float dy1 = s.y - d.y;
        const float dy2 = s.z - d.z;
        const float dy3 = s.w - d.w;

        acc += fsqrt_approx(fmaf(dx0, dx0, dy0 * dy0));
        acc += fsqrt_approx(fmaf(dx1, dx1, dy1 * dy1));
        acc += fsqrt_approx(fmaf(dx2, dx2, dy2 * dy2));
        acc += fsqrt_approx(fmaf(dx3, dx3, dy3 * dy3));

        s = d;                                    // next row's self = this d
    }

    // ── block reduce ──
    #pragma unroll
    for (int o = 16; o; o >>= 1) acc += __shfl_xor_sync(0xFFFFFFFFu, acc, o);

    __shared__ float smem[NTHR / 32];
    if (lane == 0) smem[tid >> 5] = acc;
    __syncthreads();

    if (tid < 32) {
        float v = (tid < NTHR / 32) ? smem[tid] : 0.0f;
        #pragma unroll
        for (int o = 16; o; o >>= 1) v += __shfl_xor_sync(0xFFFFFFFFu, v, o);
        if (tid == 0) g_partials[blockIdx.x] = v;
    }

    // ── last-block final reduction ──
    __shared__ bool amLast;
    if (tid == 0) {
        __threadfence();
        unsigned prev = atomicAdd(&g_count, 1u);
        amLast = (prev == (unsigned)(NBLK - 1));
    }
    __syncthreads();

    if (amLast) {
        float v = 0.0f;
        for (int i = tid; i < NBLK; i += NTHR) v += g_partials[i];
        #pragma unroll
        for (int o = 16; o; o >>= 1) v += __shfl_xor_sync(0xFFFFFFFFu, v, o);

        __shared__ float sm2[NTHR / 32];
        if (lane == 0) sm2[tid >> 5] = v;
        __syncthreads();
        if (tid < 32) {
            float w = (tid < NTHR / 32) ? sm2[tid] : 0.0f;
            #pragma unroll
            for (int o = 16; o; o >>= 1) w += __shfl_xor_sync(0xFFFFFFFFu, w, o);
            if (tid == 0) {
                out[0] = w / (float)TOTAL;
                g_count = 0;                      // reset for next graph replay
            }
        }
    }
}

extern "C" void kernel_launch(void* const* d_in, const int* in_sizes, int n_in,
                              void* d_out, int out_size) {
    tv_fused<<<NBLK, NTHR>>>((const float4*)d_in[0], (float*)d_out);
}